// round 1
// baseline (speedup 1.0000x reference)
#include <cuda_runtime.h>
#include <cstdint>
#include <cstddef>

// ---------------- problem dims (fixed) ----------------
#define I_DIM   4
#define H_DIM   2048
#define O_DIM   2
#define R_DIM   2
#define S_DIM   2
#define GB_DIM  8
#define B_DIM   32
#define T_DIM   1024
#define ALPHA_C 0.2f
#define SIGMA_C 0.05f

#define NTHREADS 512
#define EPT      4          // elements (neurons) per thread: 512*4 = 2048

// ---------------- precomputed proxy weights (device scratch) ----------------
__device__ __align__(16) float g_wi[I_DIM * H_DIM];  // alpha * wi,  layout [i][h]
__device__ __align__(16) float g_m [R_DIM * H_DIM];  // (alpha/H) * m, layout [r][h]
__device__ __align__(16) float g_n [R_DIM * H_DIM];  // n (raw),     layout [r][h]
__device__ __align__(16) float g_wo[O_DIM * H_DIM];  // wo / H,      layout [o][h]
__device__ __align__(16) float g_h0[H_DIM];

// ---------------- kernel 1: build proxies (tiny, one thread per h) ----------------
__global__ void proxy_kernel(
    const float* __restrict__ gb,     // (GB, H)
    const float* __restrict__ sup,    // (S, H)
    const float* __restrict__ wi_w,   // (I, S, GB)
    const float* __restrict__ m_w,    // (R, S, GB)
    const float* __restrict__ n_w,    // (R, S, GB)
    const float* __restrict__ wo_w,   // (O, S, GB)
    const float* __restrict__ wi_b,   // (I, S)
    const float* __restrict__ m_b,    // (R, S)
    const float* __restrict__ n_b,    // (R, S)
    const float* __restrict__ h0_w)   // (S, GB)
{
    int h = blockIdx.x * blockDim.x + threadIdx.x;
    if (h >= H_DIM) return;

    float gbh[GB_DIM];
#pragma unroll
    for (int g = 0; g < GB_DIM; ++g) gbh[g] = gb[g * H_DIM + h];
    float sv[S_DIM];
#pragma unroll
    for (int s = 0; s < S_DIM; ++s) sv[s] = sup[s * H_DIM + h];

    // wi[i,h] = sum_s sv[s]*(wi_w[i,s,:]·gbh) + wi_b[i,s]*sv[s]    (scaled by alpha)
#pragma unroll
    for (int i = 0; i < I_DIM; ++i) {
        float acc = 0.f;
#pragma unroll
        for (int s = 0; s < S_DIM; ++s) {
            float d = 0.f;
#pragma unroll
            for (int g = 0; g < GB_DIM; ++g)
                d = fmaf(wi_w[(i * S_DIM + s) * GB_DIM + g], gbh[g], d);
            acc = fmaf(sv[s], d, acc);
            acc = fmaf(wi_b[i * S_DIM + s], sv[s], acc);
        }
        g_wi[i * H_DIM + h] = ALPHA_C * acc;
    }

    // m[h,r] (scaled alpha/H) and n[h,r] (raw), both with biases
#pragma unroll
    for (int r = 0; r < R_DIM; ++r) {
        float am = 0.f, an = 0.f;
#pragma unroll
        for (int s = 0; s < S_DIM; ++s) {
            float dm = 0.f, dn = 0.f;
#pragma unroll
            for (int g = 0; g < GB_DIM; ++g) {
                dm = fmaf(m_w[(r * S_DIM + s) * GB_DIM + g], gbh[g], dm);
                dn = fmaf(n_w[(r * S_DIM + s) * GB_DIM + g], gbh[g], dn);
            }
            am = fmaf(sv[s], dm, am);
            am = fmaf(m_b[r * S_DIM + s], sv[s], am);
            an = fmaf(sv[s], dn, an);
            an = fmaf(n_b[r * S_DIM + s], sv[s], an);
        }
        g_m[r * H_DIM + h] = (ALPHA_C / (float)H_DIM) * am;
        g_n[r * H_DIM + h] = an;
    }

    // wo[h,o] (no bias), scaled 1/H
#pragma unroll
    for (int o = 0; o < O_DIM; ++o) {
        float ao = 0.f;
#pragma unroll
        for (int s = 0; s < S_DIM; ++s) {
            float d = 0.f;
#pragma unroll
            for (int g = 0; g < GB_DIM; ++g)
                d = fmaf(wo_w[(o * S_DIM + s) * GB_DIM + g], gbh[g], d);
            ao = fmaf(sv[s], d, ao);
        }
        g_wo[o * H_DIM + h] = ao * (1.0f / (float)H_DIM);
    }

    // h0[h]
    {
        float ah = 0.f;
#pragma unroll
        for (int s = 0; s < S_DIM; ++s) {
            float d = 0.f;
#pragma unroll
            for (int g = 0; g < GB_DIM; ++g)
                d = fmaf(h0_w[s * GB_DIM + g], gbh[g], d);
            ah = fmaf(sv[s], d, ah);
        }
        g_h0[h] = ah;
    }
}

// fast tanh: 1 - 2/(exp(2x)+1); ex2.approx + approx divide (~1e-7 abs err),
// saturates correctly at +-1 for large |x| (inf -> 1, 0 -> -1).
__device__ __forceinline__ float fast_tanh(float x) {
    float e;
    asm("ex2.approx.ftz.f32 %0, %1;" : "=f"(e) : "f"(x * 2.8853900817779268f));
    return 1.0f - __fdividef(2.0f, e + 1.0f);
}

// ---------------- kernel 2: sequential RNN scan, one CTA per batch ----------------
__global__ void __launch_bounds__(NTHREADS, 1)
rnn_kernel(const float* __restrict__ input,   // (B, T, I)
           const float* __restrict__ noise,   // (B, T, H)
           float* __restrict__ out,           // (B, T, O)
           float* __restrict__ traj)          // (B, T, H)
{
    const int b    = blockIdx.x;
    const int tid  = threadIdx.x;
    const int lane = tid & 31;
    const int wid  = tid >> 5;
    const int j0   = tid * EPT;

    __shared__ float4 pbuf[32];   // per-warp partials (p0,p1,q0,q1); [16..31] stay zero
    __shared__ float4 bc;         // broadcast of final reduced values

    if (tid < 32) pbuf[tid] = make_float4(0.f, 0.f, 0.f, 0.f);

    // per-element constants -> registers
    float wi_[I_DIM][EPT];
#pragma unroll
    for (int i = 0; i < I_DIM; ++i) {
        float4 v = *reinterpret_cast<const float4*>(&g_wi[i * H_DIM + j0]);
        wi_[i][0] = v.x; wi_[i][1] = v.y; wi_[i][2] = v.z; wi_[i][3] = v.w;
    }
    float m0_[EPT], m1_[EPT], n0_[EPT], n1_[EPT], wo0_[EPT], wo1_[EPT];
    {
        float4 v;
        v = *reinterpret_cast<const float4*>(&g_m[0 * H_DIM + j0]);
        m0_[0] = v.x; m0_[1] = v.y; m0_[2] = v.z; m0_[3] = v.w;
        v = *reinterpret_cast<const float4*>(&g_m[1 * H_DIM + j0]);
        m1_[0] = v.x; m1_[1] = v.y; m1_[2] = v.z; m1_[3] = v.w;
        v = *reinterpret_cast<const float4*>(&g_n[0 * H_DIM + j0]);
        n0_[0] = v.x; n0_[1] = v.y; n0_[2] = v.z; n0_[3] = v.w;
        v = *reinterpret_cast<const float4*>(&g_n[1 * H_DIM + j0]);
        n1_[0] = v.x; n1_[1] = v.y; n1_[2] = v.z; n1_[3] = v.w;
        v = *reinterpret_cast<const float4*>(&g_wo[0 * H_DIM + j0]);
        wo0_[0] = v.x; wo0_[1] = v.y; wo0_[2] = v.z; wo0_[3] = v.w;
        v = *reinterpret_cast<const float4*>(&g_wo[1 * H_DIM + j0]);
        wo1_[0] = v.x; wo1_[1] = v.y; wo1_[2] = v.z; wo1_[3] = v.w;
    }

    // state
    float h[EPT], r[EPT];
    {
        float4 v = *reinterpret_cast<const float4*>(&g_h0[j0]);
        h[0] = v.x; h[1] = v.y; h[2] = v.z; h[3] = v.w;
#pragma unroll
        for (int e = 0; e < EPT; ++e) r[e] = fast_tanh(h[e]);
    }

    const float* nrow = noise + ((size_t)b * T_DIM) * H_DIM + j0;
    const float* irow = input + (size_t)b * T_DIM * I_DIM;
    float*       trow = traj  + ((size_t)b * T_DIM) * H_DIM + j0;
    float*       orow = out   + (size_t)b * T_DIM * O_DIM;

    // prefetch step 0
    float4 nz = __ldg(reinterpret_cast<const float4*>(nrow));
    float4 iv = __ldg(reinterpret_cast<const float4*>(irow));

    __syncthreads();   // pbuf zero-init visible

    for (int t = 0; t < T_DIM; ++t) {
        // prefetch next step's noise/input (covers ~a full step of latency)
        float4 nz_n = nz, iv_n = iv;
        if (t + 1 < T_DIM) {
            nz_n = __ldg(reinterpret_cast<const float4*>(nrow + (size_t)(t + 1) * H_DIM));
            iv_n = __ldg(reinterpret_cast<const float4*>(irow + (size_t)(t + 1) * I_DIM));
        }

        // partial dot products with current r = tanh(h_{t-1}):
        //   p = n^T r   (drives this step's recurrence)
        //   q = wo^T r  (is the output of step t-1)
        float p0 = 0.f, p1 = 0.f, q0 = 0.f, q1 = 0.f;
#pragma unroll
        for (int e = 0; e < EPT; ++e) {
            p0 = fmaf(r[e], n0_[e],  p0);
            p1 = fmaf(r[e], n1_[e],  p1);
            q0 = fmaf(r[e], wo0_[e], q0);
            q1 = fmaf(r[e], wo1_[e], q1);
        }
#pragma unroll
        for (int o = 16; o > 0; o >>= 1) {
            p0 += __shfl_xor_sync(0xffffffffu, p0, o);
            p1 += __shfl_xor_sync(0xffffffffu, p1, o);
            q0 += __shfl_xor_sync(0xffffffffu, q0, o);
            q1 += __shfl_xor_sync(0xffffffffu, q1, o);
        }
        if (lane == 0) pbuf[wid] = make_float4(p0, p1, q0, q1);
        __syncthreads();

        if (wid == 0) {
            float4 v = pbuf[lane];   // lanes 16..31 read zeros
#pragma unroll
            for (int o = 16; o > 0; o >>= 1) {
                v.x += __shfl_xor_sync(0xffffffffu, v.x, o);
                v.y += __shfl_xor_sync(0xffffffffu, v.y, o);
                v.z += __shfl_xor_sync(0xffffffffu, v.z, o);
                v.w += __shfl_xor_sync(0xffffffffu, v.w, o);
            }
            if (lane == 0) bc = v;
        }
        __syncthreads();

        const float4 pv = bc;   // (p0, p1, q0, q1)

        if (tid == 0 && t > 0) {           // q is the output of the PREVIOUS step
            orow[(t - 1) * O_DIM + 0] = pv.z;
            orow[(t - 1) * O_DIM + 1] = pv.w;
        }

        // h_t = (1-a)h + a*u + sigma*noise + p0*m0' + p1*m1'
        const float nza[EPT] = {nz.x, nz.y, nz.z, nz.w};
#pragma unroll
        for (int e = 0; e < EPT; ++e) {
            float u = fmaf(iv.x, wi_[0][e],
                      fmaf(iv.y, wi_[1][e],
                      fmaf(iv.z, wi_[2][e], iv.w * wi_[3][e])));
            float acc = fmaf(nza[e], SIGMA_C, u);
            acc = fmaf(pv.x, m0_[e], acc);
            acc = fmaf(pv.y, m1_[e], acc);
            h[e] = fmaf(h[e], 1.0f - ALPHA_C, acc);
        }

        *reinterpret_cast<float4*>(trow + (size_t)t * H_DIM) =
            make_float4(h[0], h[1], h[2], h[3]);

#pragma unroll
        for (int e = 0; e < EPT; ++e) r[e] = fast_tanh(h[e]);

        nz = nz_n;
        iv = iv_n;
    }

    // final output row (t = T-1) from the last tanh(h)
    {
        float q0 = 0.f, q1 = 0.f;
#pragma unroll
        for (int e = 0; e < EPT; ++e) {
            q0 = fmaf(r[e], wo0_[e], q0);
            q1 = fmaf(r[e], wo1_[e], q1);
        }
#pragma unroll
        for (int o = 16; o > 0; o >>= 1) {
            q0 += __shfl_xor_sync(0xffffffffu, q0, o);
            q1 += __shfl_xor_sync(0xffffffffu, q1, o);
        }
        if (lane == 0) pbuf[wid] = make_float4(q0, q1, 0.f, 0.f);
        __syncthreads();
        if (wid == 0) {
            float4 v = pbuf[lane];
#pragma unroll
            for (int o = 16; o > 0; o >>= 1) {
                v.x += __shfl_xor_sync(0xffffffffu, v.x, o);
                v.y += __shfl_xor_sync(0xffffffffu, v.y, o);
            }
            if (lane == 0) {
                orow[(T_DIM - 1) * O_DIM + 0] = v.x;
                orow[(T_DIM - 1) * O_DIM + 1] = v.y;
            }
        }
    }
}

// ---------------- launcher ----------------
extern "C" void kernel_launch(void* const* d_in, const int* in_sizes, int n_in,
                              void* d_out, int out_size) {
    const float* input = (const float*)d_in[0];   // (B,T,I)
    const float* noise = (const float*)d_in[1];   // (B,T,H)
    const float* gb    = (const float*)d_in[2];   // (GB,H)
    const float* sup   = (const float*)d_in[3];   // (S,H)
    const float* wi_w  = (const float*)d_in[4];   // (I,S,GB)
    const float* m_w   = (const float*)d_in[5];   // (R,S,GB)
    const float* n_w   = (const float*)d_in[6];   // (R,S,GB)
    const float* wo_w  = (const float*)d_in[7];   // (O,S,GB)
    const float* wi_b  = (const float*)d_in[8];   // (I,S)
    const float* m_b   = (const float*)d_in[9];   // (R,S)
    const float* n_b   = (const float*)d_in[10];  // (R,S)
    const float* h0_w  = (const float*)d_in[11];  // (S,GB)

    // outputs concatenated in reference return order: output (B,T,O) then trajectories (B,T,H)
    float* out  = (float*)d_out;
    float* traj = (float*)d_out + (size_t)B_DIM * T_DIM * O_DIM;

    proxy_kernel<<<(H_DIM + 255) / 256, 256>>>(gb, sup, wi_w, m_w, n_w, wo_w,
                                               wi_b, m_b, n_b, h0_w);
    rnn_kernel<<<B_DIM, NTHREADS>>>(input, noise, out, traj);
}

// round 2
// speedup vs baseline: 1.2258x; 1.2258x over previous
#include <cuda_runtime.h>
#include <cstdint>
#include <cstddef>

// ---------------- problem dims (fixed) ----------------
#define I_DIM   4
#define H_DIM   2048
#define O_DIM   2
#define R_DIM   2
#define S_DIM   2
#define GB_DIM  8
#define B_DIM   32
#define T_DIM   1024
#define ALPHA_C 0.2f
#define SIGMA_C 0.05f

#define NTHREADS 512
#define EPT      4          // neurons per thread: 512*4 = 2048
#define NWARPS   (NTHREADS / 32)

typedef unsigned long long u64;

// ---------------- precomputed proxy weights (device scratch) ----------------
__device__ __align__(16) float g_wi[I_DIM * H_DIM];  // alpha * wi,   layout [i][h]
__device__ __align__(16) float g_m [R_DIM * H_DIM];  // (alpha/H)*m,  layout [r][h]
__device__ __align__(16) float g_n [R_DIM * H_DIM];  // n (raw),      layout [r][h]
__device__ __align__(16) float g_wo[O_DIM * H_DIM];  // wo / H,       layout [o][h]
__device__ __align__(16) float g_h0[H_DIM];

// ---------------- packed f32x2 helpers (sm_103a) ----------------
__device__ __forceinline__ u64 pack2(float lo, float hi) {
    u64 r; asm("mov.b64 %0, {%1, %2};" : "=l"(r) : "f"(lo), "f"(hi)); return r;
}
__device__ __forceinline__ u64 dup2(float x) { return pack2(x, x); }
__device__ __forceinline__ void unpack2(u64 v, float& lo, float& hi) {
    asm("mov.b64 {%0, %1}, %2;" : "=f"(lo), "=f"(hi) : "l"(v));
}
__device__ __forceinline__ u64 fma2(u64 a, u64 b, u64 c) {
    u64 d; asm("fma.rn.f32x2 %0, %1, %2, %3;" : "=l"(d) : "l"(a), "l"(b), "l"(c)); return d;
}
__device__ __forceinline__ u64 mul2(u64 a, u64 b) {
    u64 d; asm("mul.rn.f32x2 %0, %1, %2;" : "=l"(d) : "l"(a), "l"(b)); return d;
}
__device__ __forceinline__ u64 add2(u64 a, u64 b) {
    u64 d; asm("add.rn.f32x2 %0, %1, %2;" : "=l"(d) : "l"(a), "l"(b)); return d;
}
// HW tanh approximation (single MUFU op) — used only for the rank-2 recurrence dot.
__device__ __forceinline__ float tanh_hw(float x) {
    float y; asm("tanh.approx.f32 %0, %1;" : "=f"(y) : "f"(x)); return y;
}
// accurate-enough tanh (~1e-7 abs): 1 - 2/(exp(2x)+1) via ex2 + approx div
__device__ __forceinline__ float fast_tanh(float x) {
    float e;
    asm("ex2.approx.ftz.f32 %0, %1;" : "=f"(e) : "f"(x * 2.8853900817779268f));
    return 1.0f - __fdividef(2.0f, e + 1.0f);
}

// ---------------- kernel 1: build proxies ----------------
__global__ void proxy_kernel(
    const float* __restrict__ gb, const float* __restrict__ sup,
    const float* __restrict__ wi_w, const float* __restrict__ m_w,
    const float* __restrict__ n_w, const float* __restrict__ wo_w,
    const float* __restrict__ wi_b, const float* __restrict__ m_b,
    const float* __restrict__ n_b, const float* __restrict__ h0_w)
{
    int h = blockIdx.x * blockDim.x + threadIdx.x;
    if (h >= H_DIM) return;

    float gbh[GB_DIM];
#pragma unroll
    for (int g = 0; g < GB_DIM; ++g) gbh[g] = gb[g * H_DIM + h];
    float sv[S_DIM];
#pragma unroll
    for (int s = 0; s < S_DIM; ++s) sv[s] = sup[s * H_DIM + h];

#pragma unroll
    for (int i = 0; i < I_DIM; ++i) {
        float acc = 0.f;
#pragma unroll
        for (int s = 0; s < S_DIM; ++s) {
            float d = 0.f;
#pragma unroll
            for (int g = 0; g < GB_DIM; ++g)
                d = fmaf(wi_w[(i * S_DIM + s) * GB_DIM + g], gbh[g], d);
            acc = fmaf(sv[s], d, acc);
            acc = fmaf(wi_b[i * S_DIM + s], sv[s], acc);
        }
        g_wi[i * H_DIM + h] = ALPHA_C * acc;
    }

#pragma unroll
    for (int r = 0; r < R_DIM; ++r) {
        float am = 0.f, an = 0.f;
#pragma unroll
        for (int s = 0; s < S_DIM; ++s) {
            float dm = 0.f, dn = 0.f;
#pragma unroll
            for (int g = 0; g < GB_DIM; ++g) {
                dm = fmaf(m_w[(r * S_DIM + s) * GB_DIM + g], gbh[g], dm);
                dn = fmaf(n_w[(r * S_DIM + s) * GB_DIM + g], gbh[g], dn);
            }
            am = fmaf(sv[s], dm, am);
            am = fmaf(m_b[r * S_DIM + s], sv[s], am);
            an = fmaf(sv[s], dn, an);
            an = fmaf(n_b[r * S_DIM + s], sv[s], an);
        }
        g_m[r * H_DIM + h] = (ALPHA_C / (float)H_DIM) * am;
        g_n[r * H_DIM + h] = an;
    }

#pragma unroll
    for (int o = 0; o < O_DIM; ++o) {
        float ao = 0.f;
#pragma unroll
        for (int s = 0; s < S_DIM; ++s) {
            float d = 0.f;
#pragma unroll
            for (int g = 0; g < GB_DIM; ++g)
                d = fmaf(wo_w[(o * S_DIM + s) * GB_DIM + g], gbh[g], d);
            ao = fmaf(sv[s], d, ao);
        }
        g_wo[o * H_DIM + h] = ao * (1.0f / (float)H_DIM);
    }

    {
        float ah = 0.f;
#pragma unroll
        for (int s = 0; s < S_DIM; ++s) {
            float d = 0.f;
#pragma unroll
            for (int g = 0; g < GB_DIM; ++g)
                d = fmaf(h0_w[s * GB_DIM + g], gbh[g], d);
            ah = fmaf(sv[s], d, ah);
        }
        g_h0[h] = ah;
    }
}

// ---------------- kernel 2: sequential RNN scan, one CTA per batch ----------------
__global__ void __launch_bounds__(NTHREADS, 1)
rnn_kernel(const float* __restrict__ input,   // (B, T, I)
           const float* __restrict__ noise,   // (B, T, H)
           float* __restrict__ traj)          // (B, T, H)
{
    const int b    = blockIdx.x;
    const int tid  = threadIdx.x;
    const int lane = tid & 31;
    const int wid  = tid >> 5;
    const int j0   = tid * EPT;

    // double-buffered per-warp packed partials (p0,p1)
    __shared__ __align__(16) u64 pbuf[2][NWARPS];

    // --- load per-element weights, packed ---
    u64 wi_p[I_DIM][2];          // alpha*wi, pairs (e0,e1),(e2,e3)
#pragma unroll
    for (int i = 0; i < I_DIM; ++i) {
        float4 v = *reinterpret_cast<const float4*>(&g_wi[i * H_DIM + j0]);
        wi_p[i][0] = pack2(v.x, v.y);
        wi_p[i][1] = pack2(v.z, v.w);
    }
    u64 m0_p[2], m1_p[2];
    {
        float4 v;
        v = *reinterpret_cast<const float4*>(&g_m[0 * H_DIM + j0]);
        m0_p[0] = pack2(v.x, v.y); m0_p[1] = pack2(v.z, v.w);
        v = *reinterpret_cast<const float4*>(&g_m[1 * H_DIM + j0]);
        m1_p[0] = pack2(v.x, v.y); m1_p[1] = pack2(v.z, v.w);
    }
    u64 n01_p[EPT];              // per element e: (n0[e], n1[e]) packed
    {
        float4 a = *reinterpret_cast<const float4*>(&g_n[0 * H_DIM + j0]);
        float4 c = *reinterpret_cast<const float4*>(&g_n[1 * H_DIM + j0]);
        n01_p[0] = pack2(a.x, c.x);
        n01_p[1] = pack2(a.y, c.y);
        n01_p[2] = pack2(a.z, c.z);
        n01_p[3] = pack2(a.w, c.w);
    }

    const u64 SIG2 = dup2(SIGMA_C);
    const u64 C08  = dup2(1.0f - ALPHA_C);

    // --- state ---
    u64 h01, h23;
    float r0, r1, r2, r3;
    {
        float4 v = *reinterpret_cast<const float4*>(&g_h0[j0]);
        h01 = pack2(v.x, v.y);
        h23 = pack2(v.z, v.w);
        r0 = tanh_hw(v.x); r1 = tanh_hw(v.y);
        r2 = tanh_hw(v.z); r3 = tanh_hw(v.w);
    }

    const float* nrow = noise + ((size_t)b * T_DIM) * H_DIM + j0;
    const float* irow = input + (size_t)b * T_DIM * I_DIM;
    float*       trow = traj  + ((size_t)b * T_DIM) * H_DIM + j0;

    // prefetch step 0 (noise directly as packed pairs)
    ulonglong2 nz = __ldg(reinterpret_cast<const ulonglong2*>(nrow));
    float4     iv = __ldg(reinterpret_cast<const float4*>(irow));

    __syncthreads();

    for (int t = 0; t < T_DIM; ++t) {
        const int buf = t & 1;

        // prefetch next step
        ulonglong2 nz_n = nz; float4 iv_n = iv;
        if (t + 1 < T_DIM) {
            nz_n = __ldg(reinterpret_cast<const ulonglong2*>(nrow + (size_t)(t + 1) * H_DIM));
            iv_n = __ldg(reinterpret_cast<const float4*>(irow + (size_t)(t + 1) * I_DIM));
        }

        // packed dot: acc = (p0_partial, p1_partial) = sum_e r_e * (n0[e], n1[e])
        u64 acc = mul2(dup2(r3), n01_p[3]);
        acc = fma2(dup2(r2), n01_p[2], acc);
        acc = fma2(dup2(r1), n01_p[1], acc);
        acc = fma2(dup2(r0), n01_p[0], acc);

        // warp butterfly on packed value (5 rounds)
#pragma unroll
        for (int o = 16; o > 0; o >>= 1)
            acc = add2(acc, __shfl_xor_sync(0xffffffffu, acc, o));

        if (lane == 0) pbuf[buf][wid] = acc;
        __syncthreads();

        // every thread sums the 16 warp partials: 4x LDS.128 + 7 packed adds
        u64 P;
        {
            const ulonglong2* pb = reinterpret_cast<const ulonglong2*>(&pbuf[buf][0]);
            ulonglong2 a = pb[0], c = pb[1], d = pb[2], e = pb[3];
            u64 s0 = add2(a.x, a.y);
            u64 s1 = add2(c.x, c.y);
            u64 s2 = add2(d.x, d.y);
            u64 s3 = add2(e.x, e.y);
            P = add2(add2(s0, s1), add2(s2, s3));   // (p0, p1)
        }
        float p0, p1; unpack2(P, p0, p1);
        const u64 P0 = dup2(p0), P1 = dup2(p1);

        // input dups (scalar broadcast of 4 floats)
        const u64 ivx = dup2(iv.x), ivy = dup2(iv.y), ivz = dup2(iv.z), ivw = dup2(iv.w);

        // update pair (e0,e1)
        {
            u64 u = mul2(ivw, wi_p[3][0]);
            u = fma2(ivz, wi_p[2][0], u);
            u = fma2(ivy, wi_p[1][0], u);
            u = fma2(ivx, wi_p[0][0], u);
            u = fma2(nz.x, SIG2, u);
            u = fma2(P0, m0_p[0], u);
            u = fma2(P1, m1_p[0], u);
            h01 = fma2(h01, C08, u);
        }
        // update pair (e2,e3)
        {
            u64 u = mul2(ivw, wi_p[3][1]);
            u = fma2(ivz, wi_p[2][1], u);
            u = fma2(ivy, wi_p[1][1], u);
            u = fma2(ivx, wi_p[0][1], u);
            u = fma2(nz.y, SIG2, u);
            u = fma2(P0, m0_p[1], u);
            u = fma2(P1, m1_p[1], u);
            h23 = fma2(h23, C08, u);
        }

        // tanh for next step (HW approx, feeds only the rank-2 dot)
        {
            float a0, a1, a2, a3;
            unpack2(h01, a0, a1);
            unpack2(h23, a2, a3);
            r0 = tanh_hw(a0); r1 = tanh_hw(a1);
            r2 = tanh_hw(a2); r3 = tanh_hw(a3);
        }

        // store trajectory (h), 16B
        {
            ulonglong2 st; st.x = h01; st.y = h23;
            *reinterpret_cast<ulonglong2*>(trow + (size_t)t * H_DIM) = st;
        }

        nz = nz_n;
        iv = iv_n;
    }
}

// ---------------- kernel 3: outputs from trajectories (full chip, bw-bound) ----------------
#define OUT_THREADS 256
__global__ void __launch_bounds__(OUT_THREADS)
out_kernel(const float* __restrict__ traj,  // (B*T, H)
           float* __restrict__ out)         // (B*T, O)
{
    const int bt  = blockIdx.x;
    const int tid = threadIdx.x;
    const int lane = tid & 31;
    const int wid  = tid >> 5;

    const float4* row = reinterpret_cast<const float4*>(traj + (size_t)bt * H_DIM);
    const float4* w0  = reinterpret_cast<const float4*>(g_wo);
    const float4* w1  = reinterpret_cast<const float4*>(g_wo + H_DIM);

    float q0 = 0.f, q1 = 0.f;
#pragma unroll
    for (int k = 0; k < 2; ++k) {
        int idx = k * OUT_THREADS + tid;             // 0..511 float4s
        float4 v = __ldg(&row[idx]);
        float4 a = w0[idx];
        float4 c = w1[idx];
        float t0 = fast_tanh(v.x), t1 = fast_tanh(v.y);
        float t2 = fast_tanh(v.z), t3 = fast_tanh(v.w);
        q0 = fmaf(t0, a.x, fmaf(t1, a.y, fmaf(t2, a.z, fmaf(t3, a.w, q0))));
        q1 = fmaf(t0, c.x, fmaf(t1, c.y, fmaf(t2, c.z, fmaf(t3, c.w, q1))));
    }
#pragma unroll
    for (int o = 16; o > 0; o >>= 1) {
        q0 += __shfl_xor_sync(0xffffffffu, q0, o);
        q1 += __shfl_xor_sync(0xffffffffu, q1, o);
    }
    __shared__ float2 s[8];
    if (lane == 0) s[wid] = make_float2(q0, q1);
    __syncthreads();
    if (wid == 0) {
        float2 v = (lane < 8) ? s[lane] : make_float2(0.f, 0.f);
#pragma unroll
        for (int o = 4; o > 0; o >>= 1) {
            v.x += __shfl_xor_sync(0xffffffffu, v.x, o);
            v.y += __shfl_xor_sync(0xffffffffu, v.y, o);
        }
        if (lane == 0) {
            out[(size_t)bt * O_DIM + 0] = v.x;
            out[(size_t)bt * O_DIM + 1] = v.y;
        }
    }
}

// ---------------- launcher ----------------
extern "C" void kernel_launch(void* const* d_in, const int* in_sizes, int n_in,
                              void* d_out, int out_size) {
    const float* input = (const float*)d_in[0];   // (B,T,I)
    const float* noise = (const float*)d_in[1];   // (B,T,H)
    const float* gb    = (const float*)d_in[2];   // (GB,H)
    const float* sup   = (const float*)d_in[3];   // (S,H)
    const float* wi_w  = (const float*)d_in[4];   // (I,S,GB)
    const float* m_w   = (const float*)d_in[5];   // (R,S,GB)
    const float* n_w   = (const float*)d_in[6];   // (R,S,GB)
    const float* wo_w  = (const float*)d_in[7];   // (O,S,GB)
    const float* wi_b  = (const float*)d_in[8];   // (I,S)
    const float* m_b   = (const float*)d_in[9];   // (R,S)
    const float* n_b   = (const float*)d_in[10];  // (R,S)
    const float* h0_w  = (const float*)d_in[11];  // (S,GB)

    float* out  = (float*)d_out;                                   // (B,T,O)
    float* traj = (float*)d_out + (size_t)B_DIM * T_DIM * O_DIM;   // (B,T,H)

    proxy_kernel<<<(H_DIM + 255) / 256, 256>>>(gb, sup, wi_w, m_w, n_w, wo_w,
                                               wi_b, m_b, n_b, h0_w);
    rnn_kernel<<<B_DIM, NTHREADS>>>(input, noise, traj);
    out_kernel<<<B_DIM * T_DIM, OUT_THREADS>>>(traj, out);
}